// round 15
// baseline (speedup 1.0000x reference)
#include <cuda_runtime.h>
#include <cuda_bf16.h>
#include <cuda_pipeline.h>
#include <math.h>

#define LL 64
#define NB 8
#define HD 512
#define NV 8192
#define NP 2016                       // L*(L-1)/2 pairs
#define NROW ((NP + 1) * NB)          // 16136 rows (pairs + the (0,0) cell)
#define NROW_PAD (127 * 128)          // 16256, padded to GEMM row tiles
#define NEGV (-1e9f)
#define EPSV 4.5399929762484854e-05f  // exp(-10)
#define DP_SPL 8                      // l-chunks per DP column

// ------------------------- device scratch -------------------------
__device__ __nv_bfloat16 g_Atb[LL * NB * HD];    // enc @ W1t[:H]  (bf16)
__device__ __nv_bfloat16 g_Btb[LL * NB * HD];    // enc @ W1t[H:]
__device__ __nv_bfloat16 g_Awb[LL * NB * HD];    // enc @ W1w[:H]
__device__ __nv_bfloat16 g_Bwb[LL * NB * HD];    // enc @ W1w[H:]
__device__ __nv_bfloat16 g_encb[LL * NB * HD];   // enc in bf16
__device__ __nv_bfloat16 g_W1tb[2 * HD * HD];    // W1t in bf16
__device__ __nv_bfloat16 g_W1wb[2 * HD * HD];    // W1w in bf16
__device__ __nv_bfloat16 g_hwb[NROW_PAD * HD];   // relu hidden (bf16)
__device__ __nv_bfloat16 g_W2wb[HD * NV];        // W2w in bf16, k-major [k][v]
__device__ __nv_bfloat16 g_wcolT[LL * NB * HD];  // W2w columns for sentence words
__device__ float g_shlog[NP * NB];
__device__ float g_relog[NP * NB];
__device__ float g_sum[NROW_PAD];
__device__ float g_table[LL * LL * LL * NB];
__device__ volatile int g_prog[LL * DP_SPL];     // per (column, l-chunk) gap done

__device__ __forceinline__ int pidx(int i, int j) {
    return i * (2 * LL - 1 - i) / 2 + (j - i - 1);
}

__device__ __forceinline__ int inv_pair(int p, int& j) {
    int i = 0;
    while (p >= (LL - 1 - i)) { p -= (LL - 1 - i); i++; }
    j = i + 1 + p;
    return i;
}

// ------------------------- sanitized PTX helpers (no Jinja-active tokens) ------
__device__ __forceinline__ unsigned int smem_u32(const void* p) {
    unsigned int a;
    asm("{ .reg .u64 t; cvta.to.shared.u64 t, %1; cvt.u32.u64 %0, t; }"
        : "=r"(a) : "l"(p));
    return a;
}

__device__ __forceinline__ void ldsm_x4(unsigned int& r0, unsigned int& r1,
                                        unsigned int& r2, unsigned int& r3,
                                        unsigned int addr) {
    asm volatile(
        "ldmatrix.sync.aligned.m8n8.x4.shared.b16 { %0, %1, %2, %3 }, [ %4 ];"
        : "=r"(r0), "=r"(r1), "=r"(r2), "=r"(r3) : "r"(addr));
}

__device__ __forceinline__ void ldsm_x4t(unsigned int& r0, unsigned int& r1,
                                         unsigned int& r2, unsigned int& r3,
                                         unsigned int addr) {
    asm volatile(
        "ldmatrix.sync.aligned.m8n8.x4.trans.shared.b16 { %0, %1, %2, %3 }, [ %4 ];"
        : "=r"(r0), "=r"(r1), "=r"(r2), "=r"(r3) : "r"(addr));
}

__device__ __forceinline__ void mma_bf16(float& c0, float& c1, float& c2, float& c3,
                                         unsigned int a0, unsigned int a1,
                                         unsigned int a2, unsigned int a3,
                                         unsigned int b0, unsigned int b1) {
    asm volatile(
        "mma.sync.aligned.m16n8k16.row.col.f32.bf16.bf16.f32 "
        "{ %0, %1, %2, %3 }, { %4, %5, %6, %7 }, { %8, %9 }, { %0, %1, %2, %3 };"
        : "+f"(c0), "+f"(c1), "+f"(c2), "+f"(c3)
        : "r"(a0), "r"(a1), "r"(a2), "r"(a3), "r"(b0), "r"(b1));
}

// ------------------------- init + conversions (one launch) ---------------------
__global__ void init_all(const float* __restrict__ W, const float* __restrict__ enc,
                         const float* __restrict__ W1t, const float* __restrict__ W1w) {
    int idx = blockIdx.x * 256 + threadIdx.x;
    if (idx < (LL * LL * LL * NB) / 4) {
        float4 v4 = make_float4(NEGV, NEGV, NEGV, NEGV);
        *(float4*)(&g_table[idx * 4]) = v4;
    }
    if (idx < NROW_PAD / 4)
        *(float4*)(&g_sum[idx * 4]) = make_float4(0.f, 0.f, 0.f, 0.f);
    if (idx < ((NROW_PAD - NROW) * HD) / 4) {
        __nv_bfloat16 z = __float2bfloat16(0.f);
        __nv_bfloat16 o[4] = {z, z, z, z};
        *(unsigned long long*)(&g_hwb[NROW * HD + idx * 4]) = *(unsigned long long*)o;
    }
    if (idx < LL * DP_SPL) g_prog[idx] = 1;   // base cells count as gap 1
    if (idx < (HD * NV) / 4) {
        int i = idx * 4;
        float4 v = *(const float4*)(W + i);
        __nv_bfloat16 o[4];
        o[0] = __float2bfloat16(v.x);
        o[1] = __float2bfloat16(v.y);
        o[2] = __float2bfloat16(v.z);
        o[3] = __float2bfloat16(v.w);
        *(unsigned long long*)(&g_W2wb[i]) = *(unsigned long long*)o;
    }
    if (idx < (LL * NB * HD) / 4) {
        int i = idx * 4;
        float4 v = *(const float4*)(enc + i);
        __nv_bfloat16 o[4];
        o[0] = __float2bfloat16(v.x);
        o[1] = __float2bfloat16(v.y);
        o[2] = __float2bfloat16(v.z);
        o[3] = __float2bfloat16(v.w);
        *(unsigned long long*)(&g_encb[i]) = *(unsigned long long*)o;
    }
    if (idx < (2 * HD * HD) / 4) {
        int i = idx * 4;
        float4 v = *(const float4*)(W1t + i);
        __nv_bfloat16 o[4];
        o[0] = __float2bfloat16(v.x);
        o[1] = __float2bfloat16(v.y);
        o[2] = __float2bfloat16(v.z);
        o[3] = __float2bfloat16(v.w);
        *(unsigned long long*)(&g_W1tb[i]) = *(unsigned long long*)o;
        float4 w = *(const float4*)(W1w + i);
        o[0] = __float2bfloat16(w.x);
        o[1] = __float2bfloat16(w.y);
        o[2] = __float2bfloat16(w.z);
        o[3] = __float2bfloat16(w.w);
        *(unsigned long long*)(&g_W1wb[i]) = *(unsigned long long*)o;
    }
}

// ------------------------- shared GEMM tile constants --------------------------
#define AS_LD 40
#define A_BYTES (128 * AS_LD * 2)          // 10240
#define B_BYTES (32 * 128 * 2)             // 8192
#define STAGE_BYTES (A_BYTES + B_BYTES)    // 18432
#define SMEM_GEMM (3 * STAGE_BYTES)        // 55296

// ------------------------- enc projections via mma (all 4, one launch) ---------
__global__ void __launch_bounds__(256, 2) proj_mma(int dummy) {
    extern __shared__ __align__(128) char smem[];
    int which = blockIdx.z;
    const __nv_bfloat16* W = (which < 2) ? g_W1tb : g_W1wb;
    int koff = (which & 1) * HD;
    __nv_bfloat16* C = (which == 0) ? g_Atb : (which == 1) ? g_Btb
                        : (which == 2) ? g_Awb : g_Bwb;

    int tid = threadIdx.x;
    int wid = tid >> 5, lane = tid & 31;
    int wm = wid >> 2, wn = wid & 3;
    int grp = lane >> 2, qt = lane & 3;
    int rowBase = blockIdx.y * 128;
    int cb = blockIdx.x * 128;

    unsigned int aBase[3], bBase[3];
    for (int s = 0; s < 3; s++) {
        aBase[s] = smem_u32(smem + s * STAGE_BYTES);
        bBase[s] = aBase[s] + A_BYTES;
    }
    int ar0 = tid >> 2, ac0 = (tid & 3) * 8;
    int bk0 = tid >> 4, bc0 = tid & 15;

    float acc[4][4][4];
    for (int mt = 0; mt < 4; mt++)
        for (int nt = 0; nt < 4; nt++)
            for (int e = 0; e < 4; e++) acc[mt][nt][e] = 0.f;

    int am = (lane & 7) + ((lane >> 3) & 1) * 8;
    int ak = (lane >> 4) * 8;
    int bRow = lane & 15;
    int bMat = lane >> 4;

    for (int pf = 0; pf < 2; pf++) {
        char* as = smem + pf * STAGE_BYTES;
        char* bs = as + A_BYTES;
        int k0 = pf * 32;
        __pipeline_memcpy_async(as + (ar0 * AS_LD + ac0) * 2,
                                &g_encb[(rowBase + ar0) * HD + k0 + ac0], 16);
        __pipeline_memcpy_async(as + ((ar0 + 64) * AS_LD + ac0) * 2,
                                &g_encb[(rowBase + ar0 + 64) * HD + k0 + ac0], 16);
        __pipeline_memcpy_async(bs + (bk0 * 128 + ((bc0 ^ (bk0 & 7)) * 8)) * 2,
                                &W[(koff + k0 + bk0) * HD + cb + bc0 * 8], 16);
        __pipeline_memcpy_async(bs + ((bk0 + 16) * 128 + ((bc0 ^ ((bk0 + 16) & 7)) * 8)) * 2,
                                &W[(koff + k0 + bk0 + 16) * HD + cb + bc0 * 8], 16);
        __pipeline_commit();
    }

    for (int kt = 0; kt < 16; kt++) {
        if (kt < 15) __pipeline_wait_prior(1);
        else __pipeline_wait_prior(0);
        __syncthreads();
        if (kt + 2 < 16) {
            int st = (kt + 2) % 3;
            char* as = smem + st * STAGE_BYTES;
            char* bs = as + A_BYTES;
            int k0 = (kt + 2) * 32;
            __pipeline_memcpy_async(as + (ar0 * AS_LD + ac0) * 2,
                                    &g_encb[(rowBase + ar0) * HD + k0 + ac0], 16);
            __pipeline_memcpy_async(as + ((ar0 + 64) * AS_LD + ac0) * 2,
                                    &g_encb[(rowBase + ar0 + 64) * HD + k0 + ac0], 16);
            __pipeline_memcpy_async(bs + (bk0 * 128 + ((bc0 ^ (bk0 & 7)) * 8)) * 2,
                                    &W[(koff + k0 + bk0) * HD + cb + bc0 * 8], 16);
            __pipeline_memcpy_async(bs + ((bk0 + 16) * 128 + ((bc0 ^ ((bk0 + 16) & 7)) * 8)) * 2,
                                    &W[(koff + k0 + bk0 + 16) * HD + cb + bc0 * 8], 16);
            __pipeline_commit();
        }
        int st = kt % 3;
        for (int kk = 0; kk < 32; kk += 16) {
            unsigned int afr[4][4];
            for (int mt = 0; mt < 4; mt++) {
                unsigned int aaddr = aBase[st] +
                    (unsigned int)(((wm * 64 + mt * 16 + am) * AS_LD + kk + ak) * 2);
                ldsm_x4(afr[mt][0], afr[mt][1], afr[mt][2], afr[mt][3], aaddr);
            }
            unsigned int bfr[4][2];
            int br = kk + bRow;
            for (int nb2 = 0; nb2 < 2; nb2++) {
                int ntx = nb2 * 2 + bMat;
                int chunk = (wn * 4 + ntx) ^ (br & 7);
                unsigned int baddr = bBase[st] +
                    (unsigned int)((br * 128 + chunk * 8) * 2);
                ldsm_x4t(bfr[nb2 * 2][0], bfr[nb2 * 2][1],
                         bfr[nb2 * 2 + 1][0], bfr[nb2 * 2 + 1][1], baddr);
            }
            for (int mt = 0; mt < 4; mt++)
                for (int nt = 0; nt < 4; nt++)
                    mma_bf16(acc[mt][nt][0], acc[mt][nt][1],
                             acc[mt][nt][2], acc[mt][nt][3],
                             afr[mt][0], afr[mt][1], afr[mt][2], afr[mt][3],
                             bfr[nt][0], bfr[nt][1]);
        }
    }

    for (int mt = 0; mt < 4; mt++)
        for (int nt = 0; nt < 4; nt++) {
            int m0 = rowBase + wm * 64 + mt * 16 + grp;
            int c0 = cb + wn * 32 + nt * 8 + 2 * qt;
            __nv_bfloat162 h0 = __floats2bfloat162_rn(acc[mt][nt][0], acc[mt][nt][1]);
            __nv_bfloat162 h1 = __floats2bfloat162_rn(acc[mt][nt][2], acc[mt][nt][3]);
            *(__nv_bfloat162*)(&C[m0 * HD + c0]) = h0;
            *(__nv_bfloat162*)(&C[(m0 + 8) * HD + c0]) = h1;
        }
}

// ------------------------- per-pair MLP heads (+ word-column transpose) --------
__global__ void pair_kernel(const float* __restrict__ b1t, const float* __restrict__ W2t,
                            const float* __restrict__ b2t, const float* __restrict__ b1w,
                            const int* __restrict__ sentence) {
    int p = blockIdx.x;
    if (p > NP) {
        int jw = p - (NP + 1);
        for (int l = 0; l < 16; l++) {
            int idx = threadIdx.x + l * 256;   // 4096 = NB * HD
            int b = idx >> 9, h = idx & (HD - 1);
            int word = sentence[jw * NB + b];
            g_wcolT[(jw * NB + b) * HD + h] = g_W2wb[(size_t)h * NV + word];
        }
        return;
    }
    int i = 0, j = 0;
    if (p < NP) i = inv_pair(p, j);
    int w = threadIdx.x >> 5;
    int lane = threadIdx.x & 31;
    const __nv_bfloat16* Ar = &g_Awb[(i * NB + w) * HD];
    const __nv_bfloat16* Br = &g_Bwb[(j * NB + w) * HD];
    const __nv_bfloat16* At = &g_Atb[(i * NB + w) * HD];
    const __nv_bfloat16* Bt = &g_Btb[(j * NB + w) * HD];
    __nv_bfloat16* hwrow = &g_hwb[(p * NB + w) * HD];
    float part = 0.f;
    for (int t = 0; t < 16; t++) {
        int h = lane + t * 32;
        float hw = fmaxf(__bfloat162float(Ar[h]) + __bfloat162float(Br[h]) + b1w[h], 0.f);
        hwrow[h] = __float2bfloat16(hw);
        if (p < NP) {
            float ht = fmaxf(__bfloat162float(At[h]) + __bfloat162float(Bt[h]) + b1t[h], 0.f);
            part = fmaf(ht, W2t[h], part);
        }
    }
    if (p < NP) {
        for (int o = 16; o; o >>= 1) part += __shfl_xor_sync(0xffffffffu, part, o);
        if (lane == 0) {
            float z = part + b2t[0];
            float s = 1.f / (1.f + expf(-z));
            g_shlog[p * NB + w] = log1pf(-s + EPSV);
            g_relog[p * NB + w] = logf(s + EPSV);
        }
    }
}

// ------------------------- mma.sync GEMM + sum(exp) ----------------------------
__global__ void __launch_bounds__(256, 2) gemm_lse_mma(const float* __restrict__ b2w) {
    extern __shared__ __align__(128) char smem[];
    int tid = threadIdx.x;
    int wid = tid >> 5, lane = tid & 31;
    int wm = wid >> 2, wn = wid & 3;
    int grp = lane >> 2, qt = lane & 3;
    int rowBase = blockIdx.x * 128;
    int v0 = blockIdx.y * 128;

    unsigned int aBase[3], bBase[3];
    for (int s = 0; s < 3; s++) {
        aBase[s] = smem_u32(smem + s * STAGE_BYTES);
        bBase[s] = aBase[s] + A_BYTES;
    }
    int ar0 = tid >> 2, ac0 = (tid & 3) * 8;
    int bk0 = tid >> 4, bc0 = tid & 15;

    float acc[4][4][4];
    for (int mt = 0; mt < 4; mt++)
        for (int nt = 0; nt < 4; nt++)
            for (int e = 0; e < 4; e++) acc[mt][nt][e] = 0.f;

    int am = (lane & 7) + ((lane >> 3) & 1) * 8;
    int ak = (lane >> 4) * 8;
    int bRow = lane & 15;
    int bMat = lane >> 4;

    for (int pf = 0; pf < 2; pf++) {
        char* as = smem + pf * STAGE_BYTES;
        char* bs = as + A_BYTES;
        int k0 = pf * 32;
        __pipeline_memcpy_async(as + (ar0 * AS_LD + ac0) * 2,
                                &g_hwb[(rowBase + ar0) * HD + k0 + ac0], 16);
        __pipeline_memcpy_async(as + ((ar0 + 64) * AS_LD + ac0) * 2,
                                &g_hwb[(rowBase + ar0 + 64) * HD + k0 + ac0], 16);
        __pipeline_memcpy_async(bs + (bk0 * 128 + ((bc0 ^ (bk0 & 7)) * 8)) * 2,
                                &g_W2wb[(k0 + bk0) * NV + v0 + bc0 * 8], 16);
        __pipeline_memcpy_async(bs + ((bk0 + 16) * 128 + ((bc0 ^ ((bk0 + 16) & 7)) * 8)) * 2,
                                &g_W2wb[(k0 + bk0 + 16) * NV + v0 + bc0 * 8], 16);
        __pipeline_commit();
    }

    for (int kt = 0; kt < 16; kt++) {
        if (kt < 15) __pipeline_wait_prior(1);
        else __pipeline_wait_prior(0);
        __syncthreads();

        if (kt + 2 < 16) {
            int st = (kt + 2) % 3;
            char* as = smem + st * STAGE_BYTES;
            char* bs = as + A_BYTES;
            int k0 = (kt + 2) * 32;
            __pipeline_memcpy_async(as + (ar0 * AS_LD + ac0) * 2,
                                    &g_hwb[(rowBase + ar0) * HD + k0 + ac0], 16);
            __pipeline_memcpy_async(as + ((ar0 + 64) * AS_LD + ac0) * 2,
                                    &g_hwb[(rowBase + ar0 + 64) * HD + k0 + ac0], 16);
            __pipeline_memcpy_async(bs + (bk0 * 128 + ((bc0 ^ (bk0 & 7)) * 8)) * 2,
                                    &g_W2wb[(k0 + bk0) * NV + v0 + bc0 * 8], 16);
            __pipeline_memcpy_async(bs + ((bk0 + 16) * 128 + ((bc0 ^ ((bk0 + 16) & 7)) * 8)) * 2,
                                    &g_W2wb[(k0 + bk0 + 16) * NV + v0 + bc0 * 8], 16);
            __pipeline_commit();
        }

        int st = kt % 3;
        for (int kk = 0; kk < 32; kk += 16) {
            unsigned int afr[4][4];
            for (int mt = 0; mt < 4; mt++) {
                unsigned int aaddr = aBase[st] +
                    (unsigned int)(((wm * 64 + mt * 16 + am) * AS_LD + kk + ak) * 2);
                ldsm_x4(afr[mt][0], afr[mt][1], afr[mt][2], afr[mt][3], aaddr);
            }
            unsigned int bfr[4][2];
            int br = kk + bRow;
            for (int nb2 = 0; nb2 < 2; nb2++) {
                int ntx = nb2 * 2 + bMat;
                int chunk = (wn * 4 + ntx) ^ (br & 7);
                unsigned int baddr = bBase[st] +
                    (unsigned int)((br * 128 + chunk * 8) * 2);
                ldsm_x4t(bfr[nb2 * 2][0], bfr[nb2 * 2][1],
                         bfr[nb2 * 2 + 1][0], bfr[nb2 * 2 + 1][1], baddr);
            }
            for (int mt = 0; mt < 4; mt++)
                for (int nt = 0; nt < 4; nt++)
                    mma_bf16(acc[mt][nt][0], acc[mt][nt][1],
                             acc[mt][nt][2], acc[mt][nt][3],
                             afr[mt][0], afr[mt][1], afr[mt][2], afr[mt][3],
                             bfr[nt][0], bfr[nt][1]);
        }
    }

    float bw[4][2];
    for (int nt = 0; nt < 4; nt++) {
        bw[nt][0] = b2w[v0 + wn * 32 + nt * 8 + 2 * qt];
        bw[nt][1] = b2w[v0 + wn * 32 + nt * 8 + 2 * qt + 1];
    }
    for (int mt = 0; mt < 4; mt++) {
        float s0 = 0.f, s1 = 0.f;
        for (int nt = 0; nt < 4; nt++) {
            s0 += __expf(acc[mt][nt][0] + bw[nt][0]) + __expf(acc[mt][nt][1] + bw[nt][1]);
            s1 += __expf(acc[mt][nt][2] + bw[nt][0]) + __expf(acc[mt][nt][3] + bw[nt][1]);
        }
        s0 += __shfl_xor_sync(0xffffffffu, s0, 1);
        s0 += __shfl_xor_sync(0xffffffffu, s0, 2);
        s1 += __shfl_xor_sync(0xffffffffu, s1, 1);
        s1 += __shfl_xor_sync(0xffffffffu, s1, 2);
        if (qt == 0) {
            int row = rowBase + wm * 64 + mt * 16 + grp;
            atomicAdd(&g_sum[row], s0);
            atomicAdd(&g_sum[row + 8], s1);
        }
    }
}

// ------------------------- gathered word logit + DP base cells (fused) ---------
__global__ void gather_base(const int* __restrict__ sentence,
                            const float* __restrict__ b2w) {
    int row = blockIdx.x * 8 + (threadIdx.x >> 5);
    int lane = threadIdx.x & 31;
    if (row >= NROW) return;
    int p = row >> 3, b = row & 7;
    int jw, i = 0, j = 0;
    if (p < NP) { i = inv_pair(p, j); jw = (j + 1 < LL) ? j + 1 : 0; }
    else jw = 1;
    int word = sentence[jw * NB + b];
    const __nv_bfloat16* hwrow = &g_hwb[(size_t)row * HD];
    const __nv_bfloat16* wc = &g_wcolT[(jw * NB + b) * HD];
    float part = 0.f;
    for (int tt = 0; tt < 16; tt++) {
        int h = lane + tt * 32;
        part = fmaf(__bfloat162float(hwrow[h]), __bfloat162float(wc[h]), part);
    }
    for (int o = 16; o; o >>= 1) part += __shfl_xor_sync(0xffffffffu, part, o);
    if (lane == 0) {
        float gw = part + b2w[word];
        float lse = logf(g_sum[row]);
        if (p < NP) {
            if (j <= LL - 2)
                g_table[((i * LL + j) * LL + (j + 1)) * NB + b] =
                    g_shlog[row] + gw - lse;
        } else {
            g_table[(0 * LL + 1) * NB + b] = gw - lse;
        }
    }
}

// ------------------------- inside recursion: wavefront, l-split ----------------
// Column iv is split across DP_SPL blocks, each covering 8 l-values (64 thr).
// Block (iv, ls) at gap g needs foreign cells (iv, k, jv) = row l=iv of
// column k, owned by chunk iv>>3 of column k -> poll g_prog[k*DP_SPL + iv>>3].
// Deps point strictly to higher columns -> no deadlock; 496 small blocks
// all co-resident. __threadfence per gap doubles as L1 invalidate (CCTL.IVALL).
__global__ void dp_all(float* __restrict__ out) {
    int iv = blockIdx.x;
    int ls = blockIdx.y;
    int tid = threadIdx.x;
    int myChunk = iv >> 3;
    __shared__ float right[62 * 8];
    int maxgap = (LL - 1) - iv;
    int b = tid & 7, l = ls * 8 + (tid >> 3);
    const float* base = &g_table[(l * LL + iv) * LL * NB + b];
    for (int gap = 2; gap <= maxgap; gap++) {
        int jv = iv + gap;
        int nk = gap - 1;
        // wait for producers: d in [1, gap-2] needs prog[iv+d][myChunk] >= gap-d
        if (tid >= 1 && tid <= gap - 2) {
            while (g_prog[(iv + tid) * DP_SPL + myChunk] < gap - tid) {}
        }
        __syncthreads();
        if (tid == 0) __threadfence();   // acquire + L1 invalidate
        __syncthreads();

        for (int m = tid; m < nk * 8; m += 64) {
            int d = m >> 3, bb = m & 7;
            int k = iv + 1 + d;
            right[m] = g_table[((iv * LL + k) * LL + jv) * NB + bb] +
                       g_relog[pidx(k, jv) * NB + bb];
        }
        __syncthreads();
        float m0 = -3.0e38f, m1 = -3.0e38f, m2 = -3.0e38f, m3 = -3.0e38f;
        int d = 0;
        for (; d + 4 <= nk; d += 4) {
            m0 = fmaxf(m0, base[(iv + 1 + d) * NB] + right[d * 8 + b]);
            m1 = fmaxf(m1, base[(iv + 2 + d) * NB] + right[(d + 1) * 8 + b]);
            m2 = fmaxf(m2, base[(iv + 3 + d) * NB] + right[(d + 2) * 8 + b]);
            m3 = fmaxf(m3, base[(iv + 4 + d) * NB] + right[(d + 3) * 8 + b]);
        }
        for (; d < nk; d++)
            m0 = fmaxf(m0, base[(iv + 1 + d) * NB] + right[d * 8 + b]);
        float mx = fmaxf(fmaxf(m0, m1), fmaxf(m2, m3));
        float s0 = 0.f, s1 = 0.f, s2 = 0.f, s3 = 0.f;
        d = 0;
        for (; d + 4 <= nk; d += 4) {
            s0 += __expf(base[(iv + 1 + d) * NB] + right[d * 8 + b] - mx);
            s1 += __expf(base[(iv + 2 + d) * NB] + right[(d + 1) * 8 + b] - mx);
            s2 += __expf(base[(iv + 3 + d) * NB] + right[(d + 2) * 8 + b] - mx);
            s3 += __expf(base[(iv + 4 + d) * NB] + right[(d + 3) * 8 + b] - mx);
        }
        for (; d < nk; d++)
            s0 += __expf(base[(iv + 1 + d) * NB] + right[d * 8 + b] - mx);
        g_table[((l * LL + iv) * LL + jv) * NB + b] =
            mx + logf((s0 + s1) + (s2 + s3));
        __syncthreads();
        if (tid == 0) {
            __threadfence();                       // publish table writes
            g_prog[iv * DP_SPL + ls] = gap;        // release this chunk
        }
    }
    if (iv == 0 && ls == 0 && tid < NB)
        out[tid] = g_table[(0 * LL + (LL - 1)) * NB + tid];
}

// ------------------------- launch -------------------------
extern "C" void kernel_launch(void* const* d_in, const int* in_sizes, int n_in,
                              void* d_out, int out_size) {
    const float* enc = (const float*)d_in[0];
    const int* sentence = (const int*)d_in[1];
    const float* W1t = (const float*)d_in[2];
    const float* b1t = (const float*)d_in[3];
    const float* W2t = (const float*)d_in[4];
    const float* b2t = (const float*)d_in[5];
    const float* W1w = (const float*)d_in[6];
    const float* b1w = (const float*)d_in[7];
    const float* W2w = (const float*)d_in[8];
    const float* b2w = (const float*)d_in[9];
    float* out = (float*)d_out;

    cudaFuncSetAttribute(gemm_lse_mma, cudaFuncAttributeMaxDynamicSharedMemorySize,
                         SMEM_GEMM);
    cudaFuncSetAttribute(proj_mma, cudaFuncAttributeMaxDynamicSharedMemorySize,
                         SMEM_GEMM);

    init_all<<<4096, 256>>>(W2w, enc, W1t, W1w);                 // launch 1
    proj_mma<<<dim3(4, 4, 4), 256, SMEM_GEMM>>>(0);              // launch 2
    pair_kernel<<<NP + 1 + LL, 256>>>(b1t, W2t, b2t, b1w, sentence);  // launch 3
    gemm_lse_mma<<<dim3(127, 64), 256, SMEM_GEMM>>>(b2w);        // launch 4 (ncu)
    gather_base<<<(NROW + 7) / 8, 256>>>(sentence, b2w);
    dp_all<<<dim3(62, DP_SPL), 64>>>(out);
}

// round 16
// speedup vs baseline: 1.3842x; 1.3842x over previous
#include <cuda_runtime.h>
#include <cuda_bf16.h>
#include <cuda_pipeline.h>
#include <math.h>

#define LL 64
#define NB 8
#define HD 512
#define NV 8192
#define NP 2016                       // L*(L-1)/2 pairs
#define NROW ((NP + 1) * NB)          // 16136 rows (pairs + the (0,0) cell)
#define NROW_PAD (127 * 128)          // 16256, padded to GEMM row tiles
#define NEGV (-1e9f)
#define EPSV 4.5399929762484854e-05f  // exp(-10)
#define LC_K 63                       // padded k-dim for DP left-factor cache

// ------------------------- device scratch -------------------------
__device__ __nv_bfloat16 g_Atb[LL * NB * HD];    // enc @ W1t[:H]  (bf16)
__device__ __nv_bfloat16 g_Btb[LL * NB * HD];    // enc @ W1t[H:]
__device__ __nv_bfloat16 g_Awb[LL * NB * HD];    // enc @ W1w[:H]
__device__ __nv_bfloat16 g_Bwb[LL * NB * HD];    // enc @ W1w[H:]
__device__ __nv_bfloat16 g_encb[LL * NB * HD];   // enc in bf16
__device__ __nv_bfloat16 g_W1tb[2 * HD * HD];    // W1t in bf16
__device__ __nv_bfloat16 g_W1wb[2 * HD * HD];    // W1w in bf16
__device__ __nv_bfloat16 g_hwb[NROW_PAD * HD];   // relu hidden (bf16)
__device__ __nv_bfloat16 g_W2wb[HD * NV];        // W2w in bf16, k-major [k][v]
__device__ __nv_bfloat16 g_wcolT[LL * NB * HD];  // W2w columns for sentence words
__device__ float g_shlog[NP * NB];
__device__ float g_relog[NP * NB];
__device__ float g_sum[NROW_PAD];
__device__ float g_table[LL * LL * LL * NB];
__device__ volatile int g_prog[LL];              // per-column completed gap

__device__ __forceinline__ int pidx(int i, int j) {
    return i * (2 * LL - 1 - i) / 2 + (j - i - 1);
}

__device__ __forceinline__ int inv_pair(int p, int& j) {
    int i = 0;
    while (p >= (LL - 1 - i)) { p -= (LL - 1 - i); i++; }
    j = i + 1 + p;
    return i;
}

// ------------------------- sanitized PTX helpers (no Jinja-active tokens) ------
__device__ __forceinline__ unsigned int smem_u32(const void* p) {
    unsigned int a;
    asm("{ .reg .u64 t; cvta.to.shared.u64 t, %1; cvt.u32.u64 %0, t; }"
        : "=r"(a) : "l"(p));
    return a;
}

__device__ __forceinline__ void ldsm_x4(unsigned int& r0, unsigned int& r1,
                                        unsigned int& r2, unsigned int& r3,
                                        unsigned int addr) {
    asm volatile(
        "ldmatrix.sync.aligned.m8n8.x4.shared.b16 { %0, %1, %2, %3 }, [ %4 ];"
        : "=r"(r0), "=r"(r1), "=r"(r2), "=r"(r3) : "r"(addr));
}

__device__ __forceinline__ void ldsm_x4t(unsigned int& r0, unsigned int& r1,
                                         unsigned int& r2, unsigned int& r3,
                                         unsigned int addr) {
    asm volatile(
        "ldmatrix.sync.aligned.m8n8.x4.trans.shared.b16 { %0, %1, %2, %3 }, [ %4 ];"
        : "=r"(r0), "=r"(r1), "=r"(r2), "=r"(r3) : "r"(addr));
}

__device__ __forceinline__ void mma_bf16(float& c0, float& c1, float& c2, float& c3,
                                         unsigned int a0, unsigned int a1,
                                         unsigned int a2, unsigned int a3,
                                         unsigned int b0, unsigned int b1) {
    asm volatile(
        "mma.sync.aligned.m16n8k16.row.col.f32.bf16.bf16.f32 "
        "{ %0, %1, %2, %3 }, { %4, %5, %6, %7 }, { %8, %9 }, { %0, %1, %2, %3 };"
        : "+f"(c0), "+f"(c1), "+f"(c2), "+f"(c3)
        : "r"(a0), "r"(a1), "r"(a2), "r"(a3), "r"(b0), "r"(b1));
}

// ------------------------- init + conversions (one launch) ---------------------
__global__ void init_all(const float* __restrict__ W, const float* __restrict__ enc,
                         const float* __restrict__ W1t, const float* __restrict__ W1w) {
    int idx = blockIdx.x * 256 + threadIdx.x;
    if (idx < (LL * LL * LL * NB) / 4) {
        float4 v4 = make_float4(NEGV, NEGV, NEGV, NEGV);
        *(float4*)(&g_table[idx * 4]) = v4;
    }
    if (idx < NROW_PAD / 4)
        *(float4*)(&g_sum[idx * 4]) = make_float4(0.f, 0.f, 0.f, 0.f);
    if (idx < ((NROW_PAD - NROW) * HD) / 4) {
        __nv_bfloat16 z = __float2bfloat16(0.f);
        __nv_bfloat16 o[4] = {z, z, z, z};
        *(unsigned long long*)(&g_hwb[NROW * HD + idx * 4]) = *(unsigned long long*)o;
    }
    if (idx < LL) g_prog[idx] = 1;   // base cells count as gap 1
    if (idx < (HD * NV) / 4) {
        int i = idx * 4;
        float4 v = *(const float4*)(W + i);
        __nv_bfloat16 o[4];
        o[0] = __float2bfloat16(v.x);
        o[1] = __float2bfloat16(v.y);
        o[2] = __float2bfloat16(v.z);
        o[3] = __float2bfloat16(v.w);
        *(unsigned long long*)(&g_W2wb[i]) = *(unsigned long long*)o;
    }
    if (idx < (LL * NB * HD) / 4) {
        int i = idx * 4;
        float4 v = *(const float4*)(enc + i);
        __nv_bfloat16 o[4];
        o[0] = __float2bfloat16(v.x);
        o[1] = __float2bfloat16(v.y);
        o[2] = __float2bfloat16(v.z);
        o[3] = __float2bfloat16(v.w);
        *(unsigned long long*)(&g_encb[i]) = *(unsigned long long*)o;
    }
    if (idx < (2 * HD * HD) / 4) {
        int i = idx * 4;
        float4 v = *(const float4*)(W1t + i);
        __nv_bfloat16 o[4];
        o[0] = __float2bfloat16(v.x);
        o[1] = __float2bfloat16(v.y);
        o[2] = __float2bfloat16(v.z);
        o[3] = __float2bfloat16(v.w);
        *(unsigned long long*)(&g_W1tb[i]) = *(unsigned long long*)o;
        float4 w = *(const float4*)(W1w + i);
        o[0] = __float2bfloat16(w.x);
        o[1] = __float2bfloat16(w.y);
        o[2] = __float2bfloat16(w.z);
        o[3] = __float2bfloat16(w.w);
        *(unsigned long long*)(&g_W1wb[i]) = *(unsigned long long*)o;
    }
}

// ------------------------- shared GEMM tile constants --------------------------
#define AS_LD 40
#define A_BYTES (128 * AS_LD * 2)          // 10240
#define B_BYTES (32 * 128 * 2)             // 8192
#define STAGE_BYTES (A_BYTES + B_BYTES)    // 18432
#define SMEM_GEMM (3 * STAGE_BYTES)        // 55296

// ------------------------- enc projections via mma (all 4, one launch) ---------
__global__ void __launch_bounds__(256, 2) proj_mma(int dummy) {
    extern __shared__ __align__(128) char smem[];
    int which = blockIdx.z;
    const __nv_bfloat16* W = (which < 2) ? g_W1tb : g_W1wb;
    int koff = (which & 1) * HD;
    __nv_bfloat16* C = (which == 0) ? g_Atb : (which == 1) ? g_Btb
                        : (which == 2) ? g_Awb : g_Bwb;

    int tid = threadIdx.x;
    int wid = tid >> 5, lane = tid & 31;
    int wm = wid >> 2, wn = wid & 3;
    int grp = lane >> 2, qt = lane & 3;
    int rowBase = blockIdx.y * 128;
    int cb = blockIdx.x * 128;

    unsigned int aBase[3], bBase[3];
    for (int s = 0; s < 3; s++) {
        aBase[s] = smem_u32(smem + s * STAGE_BYTES);
        bBase[s] = aBase[s] + A_BYTES;
    }
    int ar0 = tid >> 2, ac0 = (tid & 3) * 8;
    int bk0 = tid >> 4, bc0 = tid & 15;

    float acc[4][4][4];
    for (int mt = 0; mt < 4; mt++)
        for (int nt = 0; nt < 4; nt++)
            for (int e = 0; e < 4; e++) acc[mt][nt][e] = 0.f;

    int am = (lane & 7) + ((lane >> 3) & 1) * 8;
    int ak = (lane >> 4) * 8;
    int bRow = lane & 15;
    int bMat = lane >> 4;

    for (int pf = 0; pf < 2; pf++) {
        char* as = smem + pf * STAGE_BYTES;
        char* bs = as + A_BYTES;
        int k0 = pf * 32;
        __pipeline_memcpy_async(as + (ar0 * AS_LD + ac0) * 2,
                                &g_encb[(rowBase + ar0) * HD + k0 + ac0], 16);
        __pipeline_memcpy_async(as + ((ar0 + 64) * AS_LD + ac0) * 2,
                                &g_encb[(rowBase + ar0 + 64) * HD + k0 + ac0], 16);
        __pipeline_memcpy_async(bs + (bk0 * 128 + ((bc0 ^ (bk0 & 7)) * 8)) * 2,
                                &W[(koff + k0 + bk0) * HD + cb + bc0 * 8], 16);
        __pipeline_memcpy_async(bs + ((bk0 + 16) * 128 + ((bc0 ^ ((bk0 + 16) & 7)) * 8)) * 2,
                                &W[(koff + k0 + bk0 + 16) * HD + cb + bc0 * 8], 16);
        __pipeline_commit();
    }

    for (int kt = 0; kt < 16; kt++) {
        if (kt < 15) __pipeline_wait_prior(1);
        else __pipeline_wait_prior(0);
        __syncthreads();
        if (kt + 2 < 16) {
            int st = (kt + 2) % 3;
            char* as = smem + st * STAGE_BYTES;
            char* bs = as + A_BYTES;
            int k0 = (kt + 2) * 32;
            __pipeline_memcpy_async(as + (ar0 * AS_LD + ac0) * 2,
                                    &g_encb[(rowBase + ar0) * HD + k0 + ac0], 16);
            __pipeline_memcpy_async(as + ((ar0 + 64) * AS_LD + ac0) * 2,
                                    &g_encb[(rowBase + ar0 + 64) * HD + k0 + ac0], 16);
            __pipeline_memcpy_async(bs + (bk0 * 128 + ((bc0 ^ (bk0 & 7)) * 8)) * 2,
                                    &W[(koff + k0 + bk0) * HD + cb + bc0 * 8], 16);
            __pipeline_memcpy_async(bs + ((bk0 + 16) * 128 + ((bc0 ^ ((bk0 + 16) & 7)) * 8)) * 2,
                                    &W[(koff + k0 + bk0 + 16) * HD + cb + bc0 * 8], 16);
            __pipeline_commit();
        }
        int st = kt % 3;
        for (int kk = 0; kk < 32; kk += 16) {
            unsigned int afr[4][4];
            for (int mt = 0; mt < 4; mt++) {
                unsigned int aaddr = aBase[st] +
                    (unsigned int)(((wm * 64 + mt * 16 + am) * AS_LD + kk + ak) * 2);
                ldsm_x4(afr[mt][0], afr[mt][1], afr[mt][2], afr[mt][3], aaddr);
            }
            unsigned int bfr[4][2];
            int br = kk + bRow;
            for (int nb2 = 0; nb2 < 2; nb2++) {
                int ntx = nb2 * 2 + bMat;
                int chunk = (wn * 4 + ntx) ^ (br & 7);
                unsigned int baddr = bBase[st] +
                    (unsigned int)((br * 128 + chunk * 8) * 2);
                ldsm_x4t(bfr[nb2 * 2][0], bfr[nb2 * 2][1],
                         bfr[nb2 * 2 + 1][0], bfr[nb2 * 2 + 1][1], baddr);
            }
            for (int mt = 0; mt < 4; mt++)
                for (int nt = 0; nt < 4; nt++)
                    mma_bf16(acc[mt][nt][0], acc[mt][nt][1],
                             acc[mt][nt][2], acc[mt][nt][3],
                             afr[mt][0], afr[mt][1], afr[mt][2], afr[mt][3],
                             bfr[nt][0], bfr[nt][1]);
        }
    }

    for (int mt = 0; mt < 4; mt++)
        for (int nt = 0; nt < 4; nt++) {
            int m0 = rowBase + wm * 64 + mt * 16 + grp;
            int c0 = cb + wn * 32 + nt * 8 + 2 * qt;
            __nv_bfloat162 h0 = __floats2bfloat162_rn(acc[mt][nt][0], acc[mt][nt][1]);
            __nv_bfloat162 h1 = __floats2bfloat162_rn(acc[mt][nt][2], acc[mt][nt][3]);
            *(__nv_bfloat162*)(&C[m0 * HD + c0]) = h0;
            *(__nv_bfloat162*)(&C[(m0 + 8) * HD + c0]) = h1;
        }
}

// ------------------------- per-pair MLP heads (+ word-column transpose) --------
__global__ void pair_kernel(const float* __restrict__ b1t, const float* __restrict__ W2t,
                            const float* __restrict__ b2t, const float* __restrict__ b1w,
                            const int* __restrict__ sentence) {
    int p = blockIdx.x;
    if (p > NP) {
        int jw = p - (NP + 1);
        for (int l = 0; l < 16; l++) {
            int idx = threadIdx.x + l * 256;   // 4096 = NB * HD
            int b = idx >> 9, h = idx & (HD - 1);
            int word = sentence[jw * NB + b];
            g_wcolT[(jw * NB + b) * HD + h] = g_W2wb[(size_t)h * NV + word];
        }
        return;
    }
    int i = 0, j = 0;
    if (p < NP) i = inv_pair(p, j);
    int w = threadIdx.x >> 5;
    int lane = threadIdx.x & 31;
    const __nv_bfloat16* Ar = &g_Awb[(i * NB + w) * HD];
    const __nv_bfloat16* Br = &g_Bwb[(j * NB + w) * HD];
    const __nv_bfloat16* At = &g_Atb[(i * NB + w) * HD];
    const __nv_bfloat16* Bt = &g_Btb[(j * NB + w) * HD];
    __nv_bfloat16* hwrow = &g_hwb[(p * NB + w) * HD];
    float part = 0.f;
    for (int t = 0; t < 16; t++) {
        int h = lane + t * 32;
        float hw = fmaxf(__bfloat162float(Ar[h]) + __bfloat162float(Br[h]) + b1w[h], 0.f);
        hwrow[h] = __float2bfloat16(hw);
        if (p < NP) {
            float ht = fmaxf(__bfloat162float(At[h]) + __bfloat162float(Bt[h]) + b1t[h], 0.f);
            part = fmaf(ht, W2t[h], part);
        }
    }
    if (p < NP) {
        for (int o = 16; o; o >>= 1) part += __shfl_xor_sync(0xffffffffu, part, o);
        if (lane == 0) {
            float z = part + b2t[0];
            float s = 1.f / (1.f + expf(-z));
            g_shlog[p * NB + w] = log1pf(-s + EPSV);
            g_relog[p * NB + w] = logf(s + EPSV);
        }
    }
}

// ------------------------- mma.sync GEMM + sum(exp) ----------------------------
__global__ void __launch_bounds__(256, 2) gemm_lse_mma(const float* __restrict__ b2w) {
    extern __shared__ __align__(128) char smem[];
    int tid = threadIdx.x;
    int wid = tid >> 5, lane = tid & 31;
    int wm = wid >> 2, wn = wid & 3;
    int grp = lane >> 2, qt = lane & 3;
    int rowBase = blockIdx.x * 128;
    int v0 = blockIdx.y * 128;

    unsigned int aBase[3], bBase[3];
    for (int s = 0; s < 3; s++) {
        aBase[s] = smem_u32(smem + s * STAGE_BYTES);
        bBase[s] = aBase[s] + A_BYTES;
    }
    int ar0 = tid >> 2, ac0 = (tid & 3) * 8;
    int bk0 = tid >> 4, bc0 = tid & 15;

    float acc[4][4][4];
    for (int mt = 0; mt < 4; mt++)
        for (int nt = 0; nt < 4; nt++)
            for (int e = 0; e < 4; e++) acc[mt][nt][e] = 0.f;

    int am = (lane & 7) + ((lane >> 3) & 1) * 8;
    int ak = (lane >> 4) * 8;
    int bRow = lane & 15;
    int bMat = lane >> 4;

    for (int pf = 0; pf < 2; pf++) {
        char* as = smem + pf * STAGE_BYTES;
        char* bs = as + A_BYTES;
        int k0 = pf * 32;
        __pipeline_memcpy_async(as + (ar0 * AS_LD + ac0) * 2,
                                &g_hwb[(rowBase + ar0) * HD + k0 + ac0], 16);
        __pipeline_memcpy_async(as + ((ar0 + 64) * AS_LD + ac0) * 2,
                                &g_hwb[(rowBase + ar0 + 64) * HD + k0 + ac0], 16);
        __pipeline_memcpy_async(bs + (bk0 * 128 + ((bc0 ^ (bk0 & 7)) * 8)) * 2,
                                &g_W2wb[(k0 + bk0) * NV + v0 + bc0 * 8], 16);
        __pipeline_memcpy_async(bs + ((bk0 + 16) * 128 + ((bc0 ^ ((bk0 + 16) & 7)) * 8)) * 2,
                                &g_W2wb[(k0 + bk0 + 16) * NV + v0 + bc0 * 8], 16);
        __pipeline_commit();
    }

    for (int kt = 0; kt < 16; kt++) {
        if (kt < 15) __pipeline_wait_prior(1);
        else __pipeline_wait_prior(0);
        __syncthreads();

        if (kt + 2 < 16) {
            int st = (kt + 2) % 3;
            char* as = smem + st * STAGE_BYTES;
            char* bs = as + A_BYTES;
            int k0 = (kt + 2) * 32;
            __pipeline_memcpy_async(as + (ar0 * AS_LD + ac0) * 2,
                                    &g_hwb[(rowBase + ar0) * HD + k0 + ac0], 16);
            __pipeline_memcpy_async(as + ((ar0 + 64) * AS_LD + ac0) * 2,
                                    &g_hwb[(rowBase + ar0 + 64) * HD + k0 + ac0], 16);
            __pipeline_memcpy_async(bs + (bk0 * 128 + ((bc0 ^ (bk0 & 7)) * 8)) * 2,
                                    &g_W2wb[(k0 + bk0) * NV + v0 + bc0 * 8], 16);
            __pipeline_memcpy_async(bs + ((bk0 + 16) * 128 + ((bc0 ^ ((bk0 + 16) & 7)) * 8)) * 2,
                                    &g_W2wb[(k0 + bk0 + 16) * NV + v0 + bc0 * 8], 16);
            __pipeline_commit();
        }

        int st = kt % 3;
        for (int kk = 0; kk < 32; kk += 16) {
            unsigned int afr[4][4];
            for (int mt = 0; mt < 4; mt++) {
                unsigned int aaddr = aBase[st] +
                    (unsigned int)(((wm * 64 + mt * 16 + am) * AS_LD + kk + ak) * 2);
                ldsm_x4(afr[mt][0], afr[mt][1], afr[mt][2], afr[mt][3], aaddr);
            }
            unsigned int bfr[4][2];
            int br = kk + bRow;
            for (int nb2 = 0; nb2 < 2; nb2++) {
                int ntx = nb2 * 2 + bMat;
                int chunk = (wn * 4 + ntx) ^ (br & 7);
                unsigned int baddr = bBase[st] +
                    (unsigned int)((br * 128 + chunk * 8) * 2);
                ldsm_x4t(bfr[nb2 * 2][0], bfr[nb2 * 2][1],
                         bfr[nb2 * 2 + 1][0], bfr[nb2 * 2 + 1][1], baddr);
            }
            for (int mt = 0; mt < 4; mt++)
                for (int nt = 0; nt < 4; nt++)
                    mma_bf16(acc[mt][nt][0], acc[mt][nt][1],
                             acc[mt][nt][2], acc[mt][nt][3],
                             afr[mt][0], afr[mt][1], afr[mt][2], afr[mt][3],
                             bfr[nt][0], bfr[nt][1]);
        }
    }

    float bw[4][2];
    for (int nt = 0; nt < 4; nt++) {
        bw[nt][0] = b2w[v0 + wn * 32 + nt * 8 + 2 * qt];
        bw[nt][1] = b2w[v0 + wn * 32 + nt * 8 + 2 * qt + 1];
    }
    for (int mt = 0; mt < 4; mt++) {
        float s0 = 0.f, s1 = 0.f;
        for (int nt = 0; nt < 4; nt++) {
            s0 += __expf(acc[mt][nt][0] + bw[nt][0]) + __expf(acc[mt][nt][1] + bw[nt][1]);
            s1 += __expf(acc[mt][nt][2] + bw[nt][0]) + __expf(acc[mt][nt][3] + bw[nt][1]);
        }
        s0 += __shfl_xor_sync(0xffffffffu, s0, 1);
        s0 += __shfl_xor_sync(0xffffffffu, s0, 2);
        s1 += __shfl_xor_sync(0xffffffffu, s1, 1);
        s1 += __shfl_xor_sync(0xffffffffu, s1, 2);
        if (qt == 0) {
            int row = rowBase + wm * 64 + mt * 16 + grp;
            atomicAdd(&g_sum[row], s0);
            atomicAdd(&g_sum[row + 8], s1);
        }
    }
}

// ------------------------- gathered word logit + DP base cells (fused) ---------
__global__ void gather_base(const int* __restrict__ sentence,
                            const float* __restrict__ b2w) {
    int row = blockIdx.x * 8 + (threadIdx.x >> 5);
    int lane = threadIdx.x & 31;
    if (row >= NROW) return;
    int p = row >> 3, b = row & 7;
    int jw, i = 0, j = 0;
    if (p < NP) { i = inv_pair(p, j); jw = (j + 1 < LL) ? j + 1 : 0; }
    else jw = 1;
    int word = sentence[jw * NB + b];
    const __nv_bfloat16* hwrow = &g_hwb[(size_t)row * HD];
    const __nv_bfloat16* wc = &g_wcolT[(jw * NB + b) * HD];
    float part = 0.f;
    for (int tt = 0; tt < 16; tt++) {
        int h = lane + tt * 32;
        part = fmaf(__bfloat162float(hwrow[h]), __bfloat162float(wc[h]), part);
    }
    for (int o = 16; o; o >>= 1) part += __shfl_xor_sync(0xffffffffu, part, o);
    if (lane == 0) {
        float gw = part + b2w[word];
        float lse = logf(g_sum[row]);
        if (p < NP) {
            if (j <= LL - 2)
                g_table[((i * LL + j) * LL + (j + 1)) * NB + b] =
                    g_shlog[row] + gw - lse;
        } else {
            g_table[(0 * LL + 1) * NB + b] = gw - lse;
        }
    }
}

// ------------------------- inside recursion: wavefront + smem left cache -------
// Block iv owns column iv (R14 structure). Left factors (l, iv, k) are the
// block's OWN outputs (plus the gap-1 base plane) -> cached in smem; thread
// (l,b) writes and reads only its own slice, so no extra syncs. k-dim padded
// to LC_K=63 (l stride 504 words = 24 mod 32 banks -> conflict-free).
// Foreign right factors stay global behind the per-gap fence.
#define SMEM_DP ((LL * LC_K * NB + 62 * NB) * 4)   // 129024 + 1984 bytes
__global__ void dp_all(float* __restrict__ out) {
    extern __shared__ float sdp[];
    float* cache = sdp;                       // [(l*LC_K + d)*8 + b]
    float* right = sdp + LL * LC_K * NB;      // [d*8 + b]
    int iv = blockIdx.x;
    int tid = threadIdx.x;
    int b = tid & 7, l = tid >> 3;
    // preload gap-1 plane: cell (l, iv, iv+1)
    cache[(l * LC_K + 0) * NB + b] =
        g_table[((l * LL + iv) * LL + iv + 1) * NB + b];
    float* myc = &cache[l * LC_K * NB + b];
    int maxgap = (LL - 1) - iv;
    for (int gap = 2; gap <= maxgap; gap++) {
        int jv = iv + gap;
        int nk = gap - 1;
        // wait for producers: d in [1, gap-2] needs prog[iv+d] >= gap-d
        if (tid >= 1 && tid <= gap - 2) {
            while (g_prog[iv + tid] < gap - tid) {}
        }
        __syncthreads();
        if (tid == 0) __threadfence();   // acquire + L1 invalidate
        __syncthreads();

        for (int m = tid; m < nk * 8; m += 512) {
            int d = m >> 3, bb = m & 7;
            int k = iv + 1 + d;
            right[m] = g_table[((iv * LL + k) * LL + jv) * NB + bb] +
                       g_relog[pidx(k, jv) * NB + bb];
        }
        __syncthreads();
        // pass 1: max (left factors from smem cache)
        float m0 = -3.0e38f, m1 = -3.0e38f, m2 = -3.0e38f, m3 = -3.0e38f;
        int d = 0;
        for (; d + 4 <= nk; d += 4) {
            m0 = fmaxf(m0, myc[d * NB] + right[d * 8 + b]);
            m1 = fmaxf(m1, myc[(d + 1) * NB] + right[(d + 1) * 8 + b]);
            m2 = fmaxf(m2, myc[(d + 2) * NB] + right[(d + 2) * 8 + b]);
            m3 = fmaxf(m3, myc[(d + 3) * NB] + right[(d + 3) * 8 + b]);
        }
        for (; d < nk; d++)
            m0 = fmaxf(m0, myc[d * NB] + right[d * 8 + b]);
        float mx = fmaxf(fmaxf(m0, m1), fmaxf(m2, m3));
        // pass 2: exp-sum
        float s0 = 0.f, s1 = 0.f, s2 = 0.f, s3 = 0.f;
        d = 0;
        for (; d + 4 <= nk; d += 4) {
            s0 += __expf(myc[d * NB] + right[d * 8 + b] - mx);
            s1 += __expf(myc[(d + 1) * NB] + right[(d + 1) * 8 + b] - mx);
            s2 += __expf(myc[(d + 2) * NB] + right[(d + 2) * 8 + b] - mx);
            s3 += __expf(myc[(d + 3) * NB] + right[(d + 3) * 8 + b] - mx);
        }
        for (; d < nk; d++)
            s0 += __expf(myc[d * NB] + right[d * 8 + b] - mx);
        float val = mx + logf((s0 + s1) + (s2 + s3));
        myc[(gap - 1) * NB] = val;                               // own left cache
        g_table[((l * LL + iv) * LL + jv) * NB + b] = val;       // publish
        __syncthreads();   // right reuse + all global writes issued
        if (tid == 0) {
            __threadfence();      // publish table writes
            g_prog[iv] = gap;     // release
        }
    }
    if (iv == 0 && tid < NB)
        out[tid] = g_table[(0 * LL + (LL - 1)) * NB + tid];
}

// ------------------------- launch -------------------------
extern "C" void kernel_launch(void* const* d_in, const int* in_sizes, int n_in,
                              void* d_out, int out_size) {
    const float* enc = (const float*)d_in[0];
    const int* sentence = (const int*)d_in[1];
    const float* W1t = (const float*)d_in[2];
    const float* b1t = (const float*)d_in[3];
    const float* W2t = (const float*)d_in[4];
    const float* b2t = (const float*)d_in[5];
    const float* W1w = (const float*)d_in[6];
    const float* b1w = (const float*)d_in[7];
    const float* W2w = (const float*)d_in[8];
    const float* b2w = (const float*)d_in[9];
    float* out = (float*)d_out;

    cudaFuncSetAttribute(gemm_lse_mma, cudaFuncAttributeMaxDynamicSharedMemorySize,
                         SMEM_GEMM);
    cudaFuncSetAttribute(proj_mma, cudaFuncAttributeMaxDynamicSharedMemorySize,
                         SMEM_GEMM);
    cudaFuncSetAttribute(dp_all, cudaFuncAttributeMaxDynamicSharedMemorySize,
                         SMEM_DP);

    init_all<<<4096, 256>>>(W2w, enc, W1t, W1w);                 // launch 1
    proj_mma<<<dim3(4, 4, 4), 256, SMEM_GEMM>>>(0);              // launch 2
    pair_kernel<<<NP + 1 + LL, 256>>>(b1t, W2t, b2t, b1w, sentence);  // launch 3
    gemm_lse_mma<<<dim3(127, 64), 256, SMEM_GEMM>>>(b2w);        // launch 4 (ncu)
    gather_base<<<(NROW + 7) / 8, 256>>>(sentence, b2w);
    dp_all<<<62, 512, SMEM_DP>>>(out);
}